// round 9
// baseline (speedup 1.0000x reference)
#include <cuda_runtime.h>
#include <cuda_bf16.h>
#include <cstdint>

#define BB    8192
#define CC    1024
#define NCLS  100
#define CAP   1024
#define NTP   3          // block pairs (0,0),(0,1),(1,1): class size <= 256
#define NCTA  (NCLS * NTP)
#define TINV  0.25f      // 1/T, T=4
#define KC    128        // fp8 elems per K-chunk (128 bytes/row)
#define NCHUNK (CC / KC) // 8
#define NSTG  4          // cp.async pipeline stages
#define PSCALE 128.0f    // fp8 storage scale: q = p*128 keeps q in e4m3 normal range

// ---- scratch (device globals: no allocations allowed) ----
__device__ uint8_t g_p8[(size_t)BB * CC];         // 8 MB fp8(e4m3) scaled probs
__device__ float g_t[BB];
__device__ int   g_cnt[NCLS];
__device__ int   g_list[NCLS * CAP];
__device__ float g_partial[NCTA];
__device__ int   g_done = 0;                      // reset by last CTA each run

// ---- helpers ----
__device__ __forceinline__ uint32_t smem_u32(const void* p) {
  uint32_t a;
  asm("{ .reg .u64 t; cvta.to.shared.u64 t, %1; cvt.u32.u64 %0, t; }" : "=r"(a) : "l"(p));
  return a;
}
__device__ __forceinline__ void cpa16(uint32_t smem_dst, const void* gsrc) {
  asm volatile("cp.async.cg.shared.global [%0], [%1], 16;" :: "r"(smem_dst), "l"(gsrc));
}
__device__ __forceinline__ void cp_commit() { asm volatile("cp.async.commit_group;"); }
template <int N> __device__ __forceinline__ void cp_wait() {
  asm volatile("cp.async.wait_group %0;" :: "n"(N));
}
__device__ __forceinline__ uint32_t swz(uint32_t b) { return b ^ ((b >> 3) & 0x70); }

__device__ __forceinline__ void ldsm_x4(uint32_t a, uint32_t& r0, uint32_t& r1,
                                        uint32_t& r2, uint32_t& r3) {
  asm volatile("ldmatrix.sync.aligned.m8n8.x4.shared.b16 {%0,%1,%2,%3}, [%4];"
               : "=r"(r0), "=r"(r1), "=r"(r2), "=r"(r3) : "r"(a));
}
// fp8 e4m3 MMA: D(16x8,f32) += A(16x32) * B(32x8); same frag distribution pattern
// as bf16 m16n8k16 at byte granularity (32B per k-step).
__device__ __forceinline__ void mma16832(float* c, uint32_t a0, uint32_t a1,
                                         uint32_t a2, uint32_t a3,
                                         uint32_t b0, uint32_t b1) {
  asm volatile(
      "mma.sync.aligned.m16n8k32.row.col.f32.e4m3.e4m3.f32 "
      "{%0,%1,%2,%3}, {%4,%5,%6,%7}, {%8,%9}, {%0,%1,%2,%3};"
      : "+f"(c[0]), "+f"(c[1]), "+f"(c[2]), "+f"(c[3])
      : "r"(a0), "r"(a1), "r"(a2), "r"(a3), "r"(b0), "r"(b1));
}

__device__ __forceinline__ uint32_t pack4_e4m3(float p0, float p1, float p2, float p3) {
  uint16_t lo, hi;
  asm("cvt.rn.satfinite.e4m3x2.f32 %0, %1, %2;" : "=h"(lo) : "f"(p1), "f"(p0));
  asm("cvt.rn.satfinite.e4m3x2.f32 %0, %1, %2;" : "=h"(hi) : "f"(p3), "f"(p2));
  return (uint32_t)lo | ((uint32_t)hi << 16);
}

__device__ __forceinline__ float warpMaxf(float v) {
#pragma unroll
  for (int o = 16; o > 0; o >>= 1) v = fmaxf(v, __shfl_xor_sync(0xffffffffu, v, o));
  return v;
}
__device__ __forceinline__ float warpSumf(float v) {
#pragma unroll
  for (int o = 16; o > 0; o >>= 1) v += __shfl_xor_sync(0xffffffffu, v, o);
  return v;
}

// exp(z) for z <= 0 via 2^w with degree-7 poly: FMA pipe only, avoids MUFU.EX2.
__device__ __forceinline__ float fast_exp(float z) {
  float w  = z * 1.4426950408889634f;
  float nf = floorf(w);
  float f  = w - nf;
  float r  = 1.5252733e-5f;
  r = fmaf(r, f, 1.5403530e-4f);
  r = fmaf(r, f, 1.3333558e-3f);
  r = fmaf(r, f, 9.6181291e-3f);
  r = fmaf(r, f, 5.5504109e-2f);
  r = fmaf(r, f, 2.4022651e-1f);
  r = fmaf(r, f, 6.9314718e-1f);
  r = fmaf(r, f, 1.0f);
  return r * __int_as_float(((int)nf + 127) << 23);
}

// ---- setup (runs inside softmax CTA 0): dtype probe + class scatter ----
// JAX with x64 disabled silently stores int64-requested targets as int32.
// True LE int64 in [0,100) => every odd 32-bit word of the first BB words is 0.
__device__ __forceinline__ void do_setup(const int* __restrict__ tgt32, int tid) {
  __shared__ int scnt[NCLS];
  __shared__ int nz;
  for (int i = tid; i < NCLS; i += 256) scnt[i] = 0;
  if (tid == 0) nz = 0;
  __syncthreads();

  int c = 0;
  for (int i = tid; i < BB / 2; i += 256)
    if (tgt32[2 * i + 1] != 0) c++;
  if (c) atomicAdd(&nz, 1);
  __syncthreads();
  int stride = (nz == 0) ? 2 : 1;   // 2 => int64 low words

  for (int i = tid; i < BB; i += 256) {
    int cl = tgt32[(size_t)i * stride];
    if ((unsigned)cl < NCLS) {
      int s = atomicAdd(&scnt[cl], 1);
      if (s < CAP) g_list[cl * CAP + s] = i;
    }
  }
  __syncthreads();
  for (int i = tid; i < NCLS; i += 256) g_cnt[i] = scnt[i];
}

// ---------------- softmax + t (warp per row) + embedded setup in CTA 0 ----------------
__global__ void __launch_bounds__(256) softmax_kernel(const float* __restrict__ x,
                                                      const int* __restrict__ tgt32) {
  if (blockIdx.x == 0) do_setup(tgt32, threadIdx.x);

  int wid = threadIdx.x >> 5, lid = threadIdx.x & 31;
  int row = blockIdx.x * 8 + wid;

  const float4* src = reinterpret_cast<const float4*>(x + (size_t)row * CC);
  float y[32];
  float m = -3.4e38f;
#pragma unroll
  for (int q = 0; q < 8; q++) {
    float4 v = src[q * 32 + lid];
    y[4 * q + 0] = v.x * TINV; y[4 * q + 1] = v.y * TINV;
    y[4 * q + 2] = v.z * TINV; y[4 * q + 3] = v.w * TINV;
    m = fmaxf(m, fmaxf(fmaxf(y[4 * q], y[4 * q + 1]), fmaxf(y[4 * q + 2], y[4 * q + 3])));
  }
  m = warpMaxf(m);

  float e[32];
  float s = 0.0f;
#pragma unroll
  for (int i = 0; i < 32; i++) { e[i] = fast_exp(y[i] - m); s += e[i]; }
  s = warpSumf(s);
  float invS = 1.0f / s;
  float lnS  = __logf(s);

  uint32_t* dst = reinterpret_cast<uint32_t*>(g_p8 + (size_t)row * CC);
  float tl = 0.0f;
#pragma unroll
  for (int q = 0; q < 8; q++) {
    float p0 = fmaf(e[4 * q + 0], invS, 1e-8f);
    float p1 = fmaf(e[4 * q + 1], invS, 1e-8f);
    float p2 = fmaf(e[4 * q + 2], invS, 1e-8f);
    float p3 = fmaf(e[4 * q + 3], invS, 1e-8f);
    // log p ~= y - m - lnS (+1e-8 shift perturbs log by ~1e-5 abs -> negligible)
    tl += p0 * (y[4 * q + 0] - m - lnS) + p1 * (y[4 * q + 1] - m - lnS)
        + p2 * (y[4 * q + 2] - m - lnS) + p3 * (y[4 * q + 3] - m - lnS);
    dst[q * 32 + lid] = pack4_e4m3(p0 * PSCALE, p1 * PSCALE, p2 * PSCALE, p3 * PSCALE);
  }
  tl = warpSumf(tl);
  if (lid == 0) g_t[row] = tl * (1.0f / CC);
}

// ---------------- per-class Gram via warp-level fp8 HMMA + fused final reduce ------
// One CTA per (class, 128-block pair). 8 warps; warp w owns rows [w*16, w*16+16).
// fp8 e4m3 scaled probs: halves LDGSTS op count (the measured bottleneck) vs bf16.
// Last CTA to finish reduces g_partial into d_out (deterministic fixed-order sum).
__global__ void __launch_bounds__(256) gram_kernel(float* __restrict__ out) {
  int c = blockIdx.y, tp = blockIdx.x;
  int g = g_cnt[c];
  if (g > 256) g = 256;
  int bi = (tp == 2) ? 1 : 0;
  int bj = (tp == 0) ? 0 : 1;
  int gA = min(g - bi * 128, 128);
  int gB = min(g - bj * 128, 128);
  bool diag = (bi == bj);
  bool active = (g >= 2) && (gA > 0) && (gB > 0);

  __shared__ __align__(1024) uint8_t sT[NSTG][128 * KC];  // 4 x 16 KB
  __shared__ int   sRA[128], sRB[128];
  __shared__ float sTA[128], sTB[128];
  __shared__ float rs[8];
  __shared__ int   sLast;

  int tid = threadIdx.x, wid = tid >> 5, lid = tid & 31;
  float total = 0.0f;

  if (active) {
    if (tid < 128) {
      int r = g_list[c * CAP + min(bi * 128 + tid, g - 1)];
      sRA[tid] = r; sTA[tid] = g_t[r];
    } else {
      int t2 = tid - 128;
      int r = g_list[c * CAP + min(bj * 128 + t2, g - 1)];
      sRB[t2] = r; sTB[t2] = g_t[r];
    }
    __syncthreads();

    // fixed per-thread load slots: 4 x (row, 16B granule) per tile
    const uint8_t* srcA[4];
    const uint8_t* srcB[4];
    uint32_t soff[4];
#pragma unroll
    for (int q = 0; q < 4; q++) {
      int s = tid + 256 * q;
      int row = s >> 3, gr = s & 7;
      srcA[q] = g_p8 + (size_t)sRA[row] * CC + gr * 16;
      srcB[q] = g_p8 + (size_t)sRB[row] * CC + gr * 16;
      soff[q] = swz((uint32_t)(row * 128 + gr * 16));
    }

    uint32_t stu[NSTG];
#pragma unroll
    for (int s = 0; s < NSTG; s++) stu[s] = smem_u32(&sT[s][0]);

    float acc[16][4];
#pragma unroll
    for (int i = 0; i < 16; i++)
#pragma unroll
      for (int j = 0; j < 4; j++) acc[i][j] = 0.0f;

    int  m0    = wid * 16;
    bool act   = (m0 < gA);
    int  nPair = (gB + 15) >> 4;   // 16-col tile pairs actually needed
    uint32_t rowAb = (uint32_t)((m0 + (lid & 15)) * 128 + (lid >> 4) * 16);
    uint32_t rowBb = (uint32_t)(((lid & 7) + ((lid >> 4) << 3)) * 128 + ((lid >> 3) & 1) * 16);

    auto compute = [&](uint32_t aB, uint32_t bB) {
      if (!act) return;
#pragma unroll
      for (int kk = 0; kk < 4; kk++) {        // 4 k32 steps per 128B chunk row
        uint32_t a0, a1, a2, a3;
        ldsm_x4(aB + swz(rowAb + kk * 32), a0, a1, a2, a3);
#pragma unroll
        for (int nt2 = 0; nt2 < 8; nt2++) {
          if (nt2 < nPair) {
            uint32_t b0, b1, b2, b3;
            ldsm_x4(bB + swz(rowBb + nt2 * 2048 + kk * 32), b0, b1, b2, b3);
            mma16832(acc[2 * nt2],     a0, a1, a2, a3, b0, b1);
            mma16832(acc[2 * nt2 + 1], a0, a1, a2, a3, b2, b3);
          }
        }
      }
    };

    if (diag) {
      // D = A.A^T: 4-stage pipeline, 3-chunk prefetch, 1 sync/chunk.
#pragma unroll
      for (int s = 0; s < NSTG - 1; s++) {
        int off = s * KC;
#pragma unroll
        for (int q = 0; q < 4; q++) cpa16(stu[s] + soff[q], srcA[q] + off);
        cp_commit();
      }
      for (int ch = 0; ch < NCHUNK; ch++) {
        cp_wait<NSTG - 2>();        // oldest pending group (chunk ch) complete
        __syncthreads();            // also: stage (ch+3)&3 consumed by all (ch-1 done)
        int pre = ch + NSTG - 1;
        if (pre < NCHUNK) {
          int off = pre * KC;
          uint32_t nxt = stu[pre & (NSTG - 1)];
#pragma unroll
          for (int q = 0; q < 4; q++) cpa16(nxt + soff[q], srcA[q] + off);
        }
        cp_commit();                // always commit: keeps group counting uniform
        uint32_t cur = stu[ch & (NSTG - 1)];
        compute(cur, cur);
      }
    } else {
      // off-diagonal (class > 128 rows; rare): A/B serial in stages 0/1
      for (int ch = 0; ch < NCHUNK; ch++) {
        int off = ch * KC;
#pragma unroll
        for (int q = 0; q < 4; q++) cpa16(stu[0] + soff[q], srcA[q] + off);
#pragma unroll
        for (int q = 0; q < 4; q++) cpa16(stu[1] + soff[q], srcB[q] + off);
        cp_commit();
        cp_wait<0>();
        __syncthreads();
        compute(stu[0], stu[1]);
        __syncthreads();
      }
    }

    // epilogue: acc[nt] C-fragment: c0=(r0,n0), c1=(r0,n0+1), c2=(r1,n0), c3=(r1,n0+1)
    float local = 0.0f;
    if (act) {
      float inv = 1.0f / ((float)CC * PSCALE * PSCALE);   // undo fp8 scaling + /n_cats
      int gid = lid >> 2, tg = lid & 3;
      int r0 = m0 + gid, r1 = r0 + 8;
      float tA0 = sTA[r0], tA1 = sTA[r1];
      bool v0 = r0 < gA, v1 = r1 < gA;
#pragma unroll
      for (int nt = 0; nt < 16; nt++) {
        int n0 = nt * 8 + tg * 2;
#pragma unroll
        for (int e2 = 0; e2 < 4; e2++) {
          int  rr = (e2 & 2) ? r1 : r0;
          bool vr = (e2 & 2) ? v1 : v0;
          int  cl = n0 + (e2 & 1);
          if (vr && (cl < gB) && (!diag || rr != cl)) {
            float cross = acc[nt][e2] * inv;
            float d = sTB[cl] - cross;          // kl[row, col]
            local += d * d;
            if (!diag) {                        // also ordered pair (col, row)
              float d2 = ((e2 & 2) ? tA1 : tA0) - cross;
              local += d2 * d2;
            }
          }
        }
      }
    }
    local = warpSumf(local);
    if (lid == 0) rs[wid] = local;
    __syncthreads();
    if (tid == 0) {
#pragma unroll
      for (int w = 0; w < 8; w++) total += rs[w];
    }
  }

  // ---- publish partial, then last-CTA-done final reduce ----
  if (tid == 0) {
    g_partial[c * NTP + tp] = total;
    __threadfence();
    int old = atomicAdd(&g_done, 1);
    sLast = (old == NCTA - 1) ? 1 : 0;
  }
  __syncthreads();
  if (sLast) {
    float s = 0.0f;
    for (int i = tid; i < NCTA; i += 256) s += g_partial[i];
    s = warpSumf(s);
    if (lid == 0) rs[wid] = s;
    __syncthreads();
    if (tid == 0) {
      float tot = 0.0f;
#pragma unroll
      for (int w = 0; w < 8; w++) tot += rs[w];
      out[0] = tot / (float)BB;
      g_done = 0;             // reset for next graph replay
    }
  }
}

extern "C" void kernel_launch(void* const* d_in, const int* in_sizes, int n_in,
                              void* d_out, int out_size) {
  const float* x;
  const int* tgt32;
  if (in_sizes[0] == BB) {       // defensive input-order detection
    tgt32 = (const int*)d_in[0];
    x     = (const float*)d_in[1];
  } else {
    x     = (const float*)d_in[0];
    tgt32 = (const int*)d_in[1];
  }

  softmax_kernel<<<BB / 8, 256>>>(x, tgt32);
  dim3 gg(NTP, NCLS);
  gram_kernel<<<gg, 256>>>((float*)d_out);
}

// round 10
// speedup vs baseline: 1.1723x; 1.1723x over previous
#include <cuda_runtime.h>
#include <cuda_bf16.h>
#include <cstdint>

#define BB    8192
#define CC    1024
#define NCLS  100
#define CAP   1024
#define NTP   3          // block pairs (0,0),(0,1),(1,1): class size <= 256
#define TINV  0.25f      // 1/T, T=4
#define KC    128        // fp8 elems per K-chunk (128 bytes/row)
#define NCHUNK (CC / KC) // 8
#define NSTG  4          // cp.async pipeline stages
#define PSCALE 128.0f    // fp8 storage scale: q = p*128 keeps q in e4m3 normal range

// ---- scratch (device globals: no allocations allowed) ----
__device__ uint8_t g_p8[(size_t)BB * CC];         // 8 MB fp8(e4m3) scaled probs
__device__ float g_t[BB];
__device__ int   g_cnt[NCLS];
__device__ int   g_list[NCLS * CAP];
__device__ float g_partial[NCLS];
__device__ int   g_done = 0;                      // reset by last CTA each run

// ---- helpers ----
__device__ __forceinline__ uint32_t smem_u32(const void* p) {
  uint32_t a;
  asm("{ .reg .u64 t; cvta.to.shared.u64 t, %1; cvt.u32.u64 %0, t; }" : "=r"(a) : "l"(p));
  return a;
}
__device__ __forceinline__ void cpa16(uint32_t smem_dst, const void* gsrc) {
  asm volatile("cp.async.cg.shared.global [%0], [%1], 16;" :: "r"(smem_dst), "l"(gsrc));
}
__device__ __forceinline__ void cp_commit() { asm volatile("cp.async.commit_group;"); }
template <int N> __device__ __forceinline__ void cp_wait() {
  asm volatile("cp.async.wait_group %0;" :: "n"(N));
}
__device__ __forceinline__ uint32_t swz(uint32_t b) { return b ^ ((b >> 3) & 0x70); }

__device__ __forceinline__ void ldsm_x4(uint32_t a, uint32_t& r0, uint32_t& r1,
                                        uint32_t& r2, uint32_t& r3) {
  asm volatile("ldmatrix.sync.aligned.m8n8.x4.shared.b16 {%0,%1,%2,%3}, [%4];"
               : "=r"(r0), "=r"(r1), "=r"(r2), "=r"(r3) : "r"(a));
}
// fp8 e4m3 MMA: D(16x8,f32) += A(16x32) * B(32x8)
__device__ __forceinline__ void mma16832(float* c, uint32_t a0, uint32_t a1,
                                         uint32_t a2, uint32_t a3,
                                         uint32_t b0, uint32_t b1) {
  asm volatile(
      "mma.sync.aligned.m16n8k32.row.col.f32.e4m3.e4m3.f32 "
      "{%0,%1,%2,%3}, {%4,%5,%6,%7}, {%8,%9}, {%0,%1,%2,%3};"
      : "+f"(c[0]), "+f"(c[1]), "+f"(c[2]), "+f"(c[3])
      : "r"(a0), "r"(a1), "r"(a2), "r"(a3), "r"(b0), "r"(b1));
}

__device__ __forceinline__ uint32_t pack4_e4m3(float p0, float p1, float p2, float p3) {
  uint16_t lo, hi;
  asm("cvt.rn.satfinite.e4m3x2.f32 %0, %1, %2;" : "=h"(lo) : "f"(p1), "f"(p0));
  asm("cvt.rn.satfinite.e4m3x2.f32 %0, %1, %2;" : "=h"(hi) : "f"(p3), "f"(p2));
  return (uint32_t)lo | ((uint32_t)hi << 16);
}

__device__ __forceinline__ float warpMaxf(float v) {
#pragma unroll
  for (int o = 16; o > 0; o >>= 1) v = fmaxf(v, __shfl_xor_sync(0xffffffffu, v, o));
  return v;
}
__device__ __forceinline__ float warpSumf(float v) {
#pragma unroll
  for (int o = 16; o > 0; o >>= 1) v += __shfl_xor_sync(0xffffffffu, v, o);
  return v;
}

// exp(z) for z <= 0 via 2^w with degree-7 poly: FMA pipe only, avoids MUFU.EX2.
__device__ __forceinline__ float fast_exp(float z) {
  float w  = z * 1.4426950408889634f;
  float nf = floorf(w);
  float f  = w - nf;
  float r  = 1.5252733e-5f;
  r = fmaf(r, f, 1.5403530e-4f);
  r = fmaf(r, f, 1.3333558e-3f);
  r = fmaf(r, f, 9.6181291e-3f);
  r = fmaf(r, f, 5.5504109e-2f);
  r = fmaf(r, f, 2.4022651e-1f);
  r = fmaf(r, f, 6.9314718e-1f);
  r = fmaf(r, f, 1.0f);
  return r * __int_as_float(((int)nf + 127) << 23);
}

// ---- setup (runs inside softmax CTA 0): dtype probe + class scatter ----
// JAX with x64 disabled silently stores int64-requested targets as int32.
// True LE int64 in [0,100) => every odd 32-bit word of the first BB words is 0.
__device__ __forceinline__ void do_setup(const int* __restrict__ tgt32, int tid) {
  __shared__ int scnt[NCLS];
  __shared__ int nz;
  for (int i = tid; i < NCLS; i += 256) scnt[i] = 0;
  if (tid == 0) nz = 0;
  __syncthreads();

  int c = 0;
  for (int i = tid; i < BB / 2; i += 256)
    if (tgt32[2 * i + 1] != 0) c++;
  if (c) atomicAdd(&nz, 1);
  __syncthreads();
  int stride = (nz == 0) ? 2 : 1;   // 2 => int64 low words

  for (int i = tid; i < BB; i += 256) {
    int cl = tgt32[(size_t)i * stride];
    if ((unsigned)cl < NCLS) {
      int s = atomicAdd(&scnt[cl], 1);
      if (s < CAP) g_list[cl * CAP + s] = i;
    }
  }
  __syncthreads();
  for (int i = tid; i < NCLS; i += 256) g_cnt[i] = scnt[i];
}

// ---------------- softmax + t (warp per row) + embedded setup in CTA 0 ----------------
__global__ void __launch_bounds__(256) softmax_kernel(const float* __restrict__ x,
                                                      const int* __restrict__ tgt32) {
  if (blockIdx.x == 0) do_setup(tgt32, threadIdx.x);

  int wid = threadIdx.x >> 5, lid = threadIdx.x & 31;
  int row = blockIdx.x * 8 + wid;

  const float4* src = reinterpret_cast<const float4*>(x + (size_t)row * CC);
  float y[32];
  float m = -3.4e38f;
#pragma unroll
  for (int q = 0; q < 8; q++) {
    float4 v = src[q * 32 + lid];
    y[4 * q + 0] = v.x * TINV; y[4 * q + 1] = v.y * TINV;
    y[4 * q + 2] = v.z * TINV; y[4 * q + 3] = v.w * TINV;
    m = fmaxf(m, fmaxf(fmaxf(y[4 * q], y[4 * q + 1]), fmaxf(y[4 * q + 2], y[4 * q + 3])));
  }
  m = warpMaxf(m);

  float e[32];
  float s = 0.0f;
#pragma unroll
  for (int i = 0; i < 32; i++) { e[i] = fast_exp(y[i] - m); s += e[i]; }
  s = warpSumf(s);
  float invS = 1.0f / s;
  float lnS  = __logf(s);

  uint32_t* dst = reinterpret_cast<uint32_t*>(g_p8 + (size_t)row * CC);
  float tl = 0.0f;
#pragma unroll
  for (int q = 0; q < 8; q++) {
    float p0 = fmaf(e[4 * q + 0], invS, 1e-8f);
    float p1 = fmaf(e[4 * q + 1], invS, 1e-8f);
    float p2 = fmaf(e[4 * q + 2], invS, 1e-8f);
    float p3 = fmaf(e[4 * q + 3], invS, 1e-8f);
    // log p ~= y - m - lnS (+1e-8 shift perturbs log by ~1e-5 abs -> negligible)
    tl += p0 * (y[4 * q + 0] - m - lnS) + p1 * (y[4 * q + 1] - m - lnS)
        + p2 * (y[4 * q + 2] - m - lnS) + p3 * (y[4 * q + 3] - m - lnS);
    dst[q * 32 + lid] = pack4_e4m3(p0 * PSCALE, p1 * PSCALE, p2 * PSCALE, p3 * PSCALE);
  }
  tl = warpSumf(tl);
  if (lid == 0) g_t[row] = tl * (1.0f / CC);
}

// ---------------- per-class Gram via warp-level fp8 HMMA + fused final reduce ------
// ONE CTA PER CLASS (grid=100 < 148 SMs => single wave, no scheduling collisions —
// the measured R6-R9 bottleneck). 512 threads / 16 warps: warp = (row-strip, N-half),
// halving each warp's ldsm+MMA chain vs 8-warp version. tp loops over tile-pairs
// inside the CTA (only (0,0) active for g<=128). Last CTA reduces into d_out.
__global__ void __launch_bounds__(512) gram_kernel(float* __restrict__ out) {
  int c = blockIdx.x;
  int g = g_cnt[c];
  if (g > 256) g = 256;

  __shared__ __align__(1024) uint8_t sT[NSTG][128 * KC];  // 4 x 16 KB
  __shared__ int   sRA[128], sRB[128];
  __shared__ float sTA[128], sTB[128];
  __shared__ float rs[16];
  __shared__ int   sLast;

  int tid = threadIdx.x, wid = tid >> 5, lid = tid & 31;
  int strip = wid >> 1;          // 0..7: 16-row strip
  int half  = wid & 1;           // 0/1: 64-col half
  float local = 0.0f;

  uint32_t stu[NSTG];
#pragma unroll
  for (int s = 0; s < NSTG; s++) stu[s] = smem_u32(&sT[s][0]);

  for (int tp = 0; tp < NTP; tp++) {
    int bi = (tp == 2) ? 1 : 0;
    int bj = (tp == 0) ? 0 : 1;
    int gA = min(g - bi * 128, 128);
    int gB = min(g - bj * 128, 128);
    if (g < 2 || gA <= 0 || gB <= 0) continue;   // uniform per CTA
    bool diag = (bi == bj);

    __syncthreads();   // previous pair's tiles/lists fully consumed
    if (tid < 128) {
      int r = g_list[c * CAP + min(bi * 128 + tid, g - 1)];
      sRA[tid] = r; sTA[tid] = g_t[r];
    } else if (tid < 256) {
      int t2 = tid - 128;
      int r = g_list[c * CAP + min(bj * 128 + t2, g - 1)];
      sRB[t2] = r; sTB[t2] = g_t[r];
    }
    __syncthreads();

    // fixed per-thread load slots: 2 x (row, 16B granule) per tile
    const uint8_t* srcA[2];
    const uint8_t* srcB[2];
    uint32_t soff[2];
#pragma unroll
    for (int q = 0; q < 2; q++) {
      int s = tid + 512 * q;
      int row = s >> 3, gr = s & 7;
      srcA[q] = g_p8 + (size_t)sRA[row] * CC + gr * 16;
      srcB[q] = g_p8 + (size_t)sRB[row] * CC + gr * 16;
      soff[q] = swz((uint32_t)(row * 128 + gr * 16));
    }

    float acc[8][4];
#pragma unroll
    for (int i = 0; i < 8; i++)
#pragma unroll
      for (int j = 0; j < 4; j++) acc[i][j] = 0.0f;

    int  m0     = strip * 16;
    int  gBh    = gB - half * 64;
    bool act    = (m0 < gA) && (gBh > 0);
    int  nPairH = min((gBh + 15) >> 4, 4);
    uint32_t rowAb = (uint32_t)((m0 + (lid & 15)) * 128 + (lid >> 4) * 16);
    uint32_t rowBb = (uint32_t)(((lid & 7) + ((lid >> 4) << 3)) * 128
                                + ((lid >> 3) & 1) * 16 + half * 64 * 128);

    auto compute = [&](uint32_t aB, uint32_t bB) {
      if (!act) return;
#pragma unroll
      for (int kk = 0; kk < 4; kk++) {        // 4 k32 steps per 128B chunk row
        uint32_t a0, a1, a2, a3;
        ldsm_x4(aB + swz(rowAb + kk * 32), a0, a1, a2, a3);
        uint32_t b[4][4];
#pragma unroll
        for (int nt2 = 0; nt2 < 4; nt2++)
          if (nt2 < nPairH)
            ldsm_x4(bB + swz(rowBb + nt2 * 2048 + kk * 32),
                    b[nt2][0], b[nt2][1], b[nt2][2], b[nt2][3]);
#pragma unroll
        for (int nt2 = 0; nt2 < 4; nt2++) {
          if (nt2 < nPairH) {
            mma16832(acc[2 * nt2],     a0, a1, a2, a3, b[nt2][0], b[nt2][1]);
            mma16832(acc[2 * nt2 + 1], a0, a1, a2, a3, b[nt2][2], b[nt2][3]);
          }
        }
      }
    };

    if (diag) {
      // D = A.A^T: 4-stage pipeline, 3-chunk prefetch, 1 sync/chunk.
#pragma unroll
      for (int s = 0; s < NSTG - 1; s++) {
        int off = s * KC;
#pragma unroll
        for (int q = 0; q < 2; q++) cpa16(stu[s] + soff[q], srcA[q] + off);
        cp_commit();
      }
      for (int ch = 0; ch < NCHUNK; ch++) {
        cp_wait<NSTG - 2>();        // oldest pending group (chunk ch) complete
        __syncthreads();            // stage (ch+3)&3 consumed by all (ch-1 done)
        int pre = ch + NSTG - 1;
        if (pre < NCHUNK) {
          int off = pre * KC;
          uint32_t nxt = stu[pre & (NSTG - 1)];
#pragma unroll
          for (int q = 0; q < 2; q++) cpa16(nxt + soff[q], srcA[q] + off);
        }
        cp_commit();                // always commit: keeps group counting uniform
        uint32_t cur = stu[ch & (NSTG - 1)];
        compute(cur, cur);
      }
      cp_wait<0>();
    } else {
      // off-diagonal (class > 128 rows; rare): A/B serial in stages 0/1
      for (int ch = 0; ch < NCHUNK; ch++) {
        int off = ch * KC;
#pragma unroll
        for (int q = 0; q < 2; q++) cpa16(stu[0] + soff[q], srcA[q] + off);
#pragma unroll
        for (int q = 0; q < 2; q++) cpa16(stu[1] + soff[q], srcB[q] + off);
        cp_commit();
        cp_wait<0>();
        __syncthreads();
        compute(stu[0], stu[1]);
        __syncthreads();
      }
    }

    // epilogue: acc[nt] C-frag: c0=(r0,n0), c1=(r0,n0+1), c2=(r1,n0), c3=(r1,n0+1)
    if (act) {
      float inv = 1.0f / ((float)CC * PSCALE * PSCALE);   // undo fp8 scale + /n_cats
      int gid = lid >> 2, tg = lid & 3;
      int r0 = m0 + gid, r1 = r0 + 8;
      float tA0 = sTA[r0], tA1 = sTA[r1];
      bool v0 = r0 < gA, v1 = r1 < gA;
#pragma unroll
      for (int nt = 0; nt < 8; nt++) {
        int n0 = half * 64 + nt * 8 + tg * 2;
#pragma unroll
        for (int e2 = 0; e2 < 4; e2++) {
          int  rr = (e2 & 2) ? r1 : r0;
          bool vr = (e2 & 2) ? v1 : v0;
          int  cl = n0 + (e2 & 1);
          if (vr && (cl < gB) && (!diag || rr != cl)) {
            float cross = acc[nt][e2] * inv;
            float d = sTB[cl] - cross;          // kl[row, col]
            local += d * d;
            if (!diag) {                        // also ordered pair (col, row)
              float d2 = ((e2 & 2) ? tA1 : tA0) - cross;
              local += d2 * d2;
            }
          }
        }
      }
    }
  }

  // ---- block reduce, publish partial, last-CTA final reduce ----
  local = warpSumf(local);
  if (lid == 0) rs[wid] = local;
  __syncthreads();
  float total = 0.0f;
  if (tid == 0) {
#pragma unroll
    for (int w = 0; w < 16; w++) total += rs[w];
    g_partial[c] = total;
    __threadfence();
    int old = atomicAdd(&g_done, 1);
    sLast = (old == NCLS - 1) ? 1 : 0;
  }
  __syncthreads();
  if (sLast) {
    float s = 0.0f;
    for (int i = tid; i < NCLS; i += 512) s += g_partial[i];
    s = warpSumf(s);
    if (lid == 0) rs[wid] = s;
    __syncthreads();
    if (tid == 0) {
      float tot = 0.0f;
#pragma unroll
      for (int w = 0; w < 16; w++) tot += rs[w];
      out[0] = tot / (float)BB;
      g_done = 0;             // reset for next graph replay
    }
  }
}

extern "C" void kernel_launch(void* const* d_in, const int* in_sizes, int n_in,
                              void* d_out, int out_size) {
  const float* x;
  const int* tgt32;
  if (in_sizes[0] == BB) {       // defensive input-order detection
    tgt32 = (const int*)d_in[0];
    x     = (const float*)d_in[1];
  } else {
    x     = (const float*)d_in[0];
    tgt32 = (const int*)d_in[1];
  }

  softmax_kernel<<<BB / 8, 256>>>(x, tgt32);
  gram_kernel<<<NCLS, 512>>>((float*)d_out);
}

// round 11
// speedup vs baseline: 1.3248x; 1.1301x over previous
#include <cuda_runtime.h>
#include <cuda_bf16.h>
#include <cstdint>

#define BB    8192
#define CC    1024
#define NCLS  100
#define CAP   1024
#define NTP   3          // block pairs (0,0),(0,1),(1,1): class size <= 256
#define TINV  0.25f      // 1/T, T=4
#define KC    128        // fp8 elems per K-chunk (128 bytes/row)
#define NCHUNK (CC / KC) // 8
#define NSTG  4          // cp.async pipeline stages
#define PSCALE 128.0f    // fp8 storage scale: q = p*128 keeps q in e4m3 normal range
#define NT    4          // max tiles per warp

// ---- scratch (device globals: no allocations allowed) ----
__device__ uint8_t g_p8[(size_t)BB * CC];         // 8 MB fp8(e4m3) scaled probs
__device__ float g_t[BB];
__device__ int   g_cnt[NCLS];
__device__ int   g_list[NCLS * CAP];
__device__ float g_partial[NCLS];
__device__ int   g_done = 0;                      // reset by last CTA each run

// ---- helpers ----
__device__ __forceinline__ uint32_t smem_u32(const void* p) {
  uint32_t a;
  asm("{ .reg .u64 t; cvta.to.shared.u64 t, %1; cvt.u32.u64 %0, t; }" : "=r"(a) : "l"(p));
  return a;
}
__device__ __forceinline__ void cpa16(uint32_t smem_dst, const void* gsrc) {
  asm volatile("cp.async.cg.shared.global [%0], [%1], 16;" :: "r"(smem_dst), "l"(gsrc));
}
__device__ __forceinline__ void cp_commit() { asm volatile("cp.async.commit_group;"); }
template <int N> __device__ __forceinline__ void cp_wait() {
  asm volatile("cp.async.wait_group %0;" :: "n"(N));
}
__device__ __forceinline__ uint32_t swz(uint32_t b) { return b ^ ((b >> 3) & 0x70); }

__device__ __forceinline__ void ldsm_x4(uint32_t a, uint32_t& r0, uint32_t& r1,
                                        uint32_t& r2, uint32_t& r3) {
  asm volatile("ldmatrix.sync.aligned.m8n8.x4.shared.b16 {%0,%1,%2,%3}, [%4];"
               : "=r"(r0), "=r"(r1), "=r"(r2), "=r"(r3) : "r"(a));
}
// fp8 e4m3 MMA: D(16x8,f32) += A(16x32) * B(32x8)
__device__ __forceinline__ void mma16832(float* c, uint32_t a0, uint32_t a1,
                                         uint32_t a2, uint32_t a3,
                                         uint32_t b0, uint32_t b1) {
  asm volatile(
      "mma.sync.aligned.m16n8k32.row.col.f32.e4m3.e4m3.f32 "
      "{%0,%1,%2,%3}, {%4,%5,%6,%7}, {%8,%9}, {%0,%1,%2,%3};"
      : "+f"(c[0]), "+f"(c[1]), "+f"(c[2]), "+f"(c[3])
      : "r"(a0), "r"(a1), "r"(a2), "r"(a3), "r"(b0), "r"(b1));
}

__device__ __forceinline__ uint32_t pack4_e4m3(float p0, float p1, float p2, float p3) {
  uint16_t lo, hi;
  asm("cvt.rn.satfinite.e4m3x2.f32 %0, %1, %2;" : "=h"(lo) : "f"(p1), "f"(p0));
  asm("cvt.rn.satfinite.e4m3x2.f32 %0, %1, %2;" : "=h"(hi) : "f"(p3), "f"(p2));
  return (uint32_t)lo | ((uint32_t)hi << 16);
}

__device__ __forceinline__ float warpMaxf(float v) {
#pragma unroll
  for (int o = 16; o > 0; o >>= 1) v = fmaxf(v, __shfl_xor_sync(0xffffffffu, v, o));
  return v;
}
__device__ __forceinline__ float warpSumf(float v) {
#pragma unroll
  for (int o = 16; o > 0; o >>= 1) v += __shfl_xor_sync(0xffffffffu, v, o);
  return v;
}

// exp(z) for z <= 0 via 2^w with degree-7 poly: FMA pipe only, avoids MUFU.EX2.
__device__ __forceinline__ float fast_exp(float z) {
  float w  = z * 1.4426950408889634f;
  float nf = floorf(w);
  float f  = w - nf;
  float r  = 1.5252733e-5f;
  r = fmaf(r, f, 1.5403530e-4f);
  r = fmaf(r, f, 1.3333558e-3f);
  r = fmaf(r, f, 9.6181291e-3f);
  r = fmaf(r, f, 5.5504109e-2f);
  r = fmaf(r, f, 2.4022651e-1f);
  r = fmaf(r, f, 6.9314718e-1f);
  r = fmaf(r, f, 1.0f);
  return r * __int_as_float(((int)nf + 127) << 23);
}

// ---- setup (runs inside softmax CTA 0): dtype probe + class scatter ----
// JAX with x64 disabled silently stores int64-requested targets as int32.
// True LE int64 in [0,100) => every odd 32-bit word of the first BB words is 0.
__device__ __forceinline__ void do_setup(const int* __restrict__ tgt32, int tid) {
  __shared__ int scnt[NCLS];
  __shared__ int nz;
  for (int i = tid; i < NCLS; i += 256) scnt[i] = 0;
  if (tid == 0) nz = 0;
  __syncthreads();

  int c = 0;
  for (int i = tid; i < BB / 2; i += 256)
    if (tgt32[2 * i + 1] != 0) c++;
  if (c) atomicAdd(&nz, 1);
  __syncthreads();
  int stride = (nz == 0) ? 2 : 1;   // 2 => int64 low words

  for (int i = tid; i < BB; i += 256) {
    int cl = tgt32[(size_t)i * stride];
    if ((unsigned)cl < NCLS) {
      int s = atomicAdd(&scnt[cl], 1);
      if (s < CAP) g_list[cl * CAP + s] = i;
    }
  }
  __syncthreads();
  for (int i = tid; i < NCLS; i += 256) g_cnt[i] = scnt[i];
}

// ---------------- softmax + t (warp per row) + embedded setup in CTA 0 ----------------
__global__ void __launch_bounds__(256) softmax_kernel(const float* __restrict__ x,
                                                      const int* __restrict__ tgt32) {
  if (blockIdx.x == 0) do_setup(tgt32, threadIdx.x);

  int wid = threadIdx.x >> 5, lid = threadIdx.x & 31;
  int row = blockIdx.x * 8 + wid;

  const float4* src = reinterpret_cast<const float4*>(x + (size_t)row * CC);
  float y[32];
  float m = -3.4e38f;
#pragma unroll
  for (int q = 0; q < 8; q++) {
    float4 v = src[q * 32 + lid];
    y[4 * q + 0] = v.x * TINV; y[4 * q + 1] = v.y * TINV;
    y[4 * q + 2] = v.z * TINV; y[4 * q + 3] = v.w * TINV;
    m = fmaxf(m, fmaxf(fmaxf(y[4 * q], y[4 * q + 1]), fmaxf(y[4 * q + 2], y[4 * q + 3])));
  }
  m = warpMaxf(m);

  float e[32];
  float s = 0.0f;
#pragma unroll
  for (int i = 0; i < 32; i++) { e[i] = fast_exp(y[i] - m); s += e[i]; }
  s = warpSumf(s);
  float invS = 1.0f / s;
  float lnS  = __logf(s);

  uint32_t* dst = reinterpret_cast<uint32_t*>(g_p8 + (size_t)row * CC);
  float tl = 0.0f;
#pragma unroll
  for (int q = 0; q < 8; q++) {
    float p0 = fmaf(e[4 * q + 0], invS, 1e-8f);
    float p1 = fmaf(e[4 * q + 1], invS, 1e-8f);
    float p2 = fmaf(e[4 * q + 2], invS, 1e-8f);
    float p3 = fmaf(e[4 * q + 3], invS, 1e-8f);
    // log p ~= y - m - lnS (+1e-8 shift perturbs log by ~1e-5 abs -> negligible)
    tl += p0 * (y[4 * q + 0] - m - lnS) + p1 * (y[4 * q + 1] - m - lnS)
        + p2 * (y[4 * q + 2] - m - lnS) + p3 * (y[4 * q + 3] - m - lnS);
    dst[q * 32 + lid] = pack4_e4m3(p0 * PSCALE, p1 * PSCALE, p2 * PSCALE, p3 * PSCALE);
  }
  tl = warpSumf(tl);
  if (lid == 0) g_t[row] = tl * (1.0f / CC);
}

// ---------------- per-class Gram via fp8 HMMA, SYMMETRIC upper-triangle only ------
// One CTA per class (grid=100, single wave). 512 threads / 16 warps. Work unit =
// 16x16 D tile; for the diagonal block pair only the 36 upper-triangle tiles are
// computed (Gram symmetry) -- the mma.sync fallback MAC throughput is the measured
// R6-R10 ceiling, so fewer MACs is the only lever. Tiles round-robin over warps.
__global__ void __launch_bounds__(512) gram_kernel(float* __restrict__ out) {
  int c = blockIdx.x;
  int g = g_cnt[c];
  if (g > 256) g = 256;

  __shared__ __align__(1024) uint8_t sT[NSTG][128 * KC];  // 4 x 16 KB
  __shared__ int   sRA[128], sRB[128];
  __shared__ float sTA[128], sTB[128];
  __shared__ float rs[16];
  __shared__ int   sLast;

  int tid = threadIdx.x, wid = tid >> 5, lid = tid & 31;
  float local = 0.0f;

  uint32_t stu[NSTG];
#pragma unroll
  for (int s = 0; s < NSTG; s++) stu[s] = smem_u32(&sT[s][0]);

  for (int tp = 0; tp < NTP; tp++) {
    int bi = (tp == 2) ? 1 : 0;
    int bj = (tp == 0) ? 0 : 1;
    int gA = min(g - bi * 128, 128);
    int gB = min(g - bj * 128, 128);
    if (g < 2 || gA <= 0 || gB <= 0) continue;   // uniform per CTA
    bool diag = (bi == bj);

    __syncthreads();   // previous pair's tiles/lists fully consumed
    if (tid < 128) {
      int r = g_list[c * CAP + min(bi * 128 + tid, g - 1)];
      sRA[tid] = r; sTA[tid] = g_t[r];
    } else if (tid < 256) {
      int t2 = tid - 128;
      int r = g_list[c * CAP + min(bj * 128 + t2, g - 1)];
      sRB[t2] = r; sTB[t2] = g_t[r];
    }
    __syncthreads();

    // fixed per-thread load slots: 2 x (row, 16B granule) per tile
    const uint8_t* srcA[2];
    const uint8_t* srcB[2];
    uint32_t soff[2];
#pragma unroll
    for (int q = 0; q < 2; q++) {
      int s = tid + 512 * q;
      int row = s >> 3, gr = s & 7;
      srcA[q] = g_p8 + (size_t)sRA[row] * CC + gr * 16;
      srcB[q] = g_p8 + (size_t)sRB[row] * CC + gr * 16;
      soff[q] = swz((uint32_t)(row * 128 + gr * 16));
    }

    // ---- per-warp tile list: diag => 36 upper-triangle tiles, else 8x8=64 ----
    int  tI[NT], tJ[NT];
    bool tV[NT];
    int  nlist = diag ? 36 : 64;
    for (int tt = 0; tt < NT; tt++) {
      int t = wid + tt * 16;
      bool ex = t < nlist;
      int i = 0, j = 0;
      if (ex) {
        if (diag) { int rem = t; while (rem >= 8 - i) { rem -= 8 - i; i++; } j = i + rem; }
        else      { i = t >> 3; j = t & 7; }
      }
      tI[tt] = i; tJ[tt] = j;
      tV[tt] = ex && (16 * i < gA) && (16 * j < gB);
    }

    float acc[NT][2][4];
#pragma unroll
    for (int tt = 0; tt < NT; tt++)
#pragma unroll
      for (int mhalf = 0; mhalf < 2; mhalf++)
#pragma unroll
        for (int e2 = 0; e2 < 4; e2++) acc[tt][mhalf][e2] = 0.0f;

    // ldmatrix lane address components (bytes within tile)
    uint32_t aoff[NT], boff[NT];
    uint32_t aLane = (uint32_t)((lid & 15) * 128 + (lid >> 4) * 16);
    uint32_t bLane = (uint32_t)(((lid & 7) + ((lid >> 4) << 3)) * 128 + ((lid >> 3) & 1) * 16);
#pragma unroll
    for (int tt = 0; tt < NT; tt++) {
      aoff[tt] = aLane + (uint32_t)(tI[tt] * 16 * 128);
      boff[tt] = bLane + (uint32_t)(tJ[tt] * 16 * 128);
    }

    auto compute = [&](uint32_t aB, uint32_t bB) {
#pragma unroll
      for (int kk = 0; kk < 4; kk++) {        // 4 k32 steps per 128B chunk row
#pragma unroll
        for (int tt = 0; tt < NT; tt++) {
          if (tV[tt]) {
            uint32_t a0, a1, a2, a3, b0, b1, b2, b3;
            ldsm_x4(aB + swz(aoff[tt] + kk * 32), a0, a1, a2, a3);
            ldsm_x4(bB + swz(boff[tt] + kk * 32), b0, b1, b2, b3);
            mma16832(acc[tt][0], a0, a1, a2, a3, b0, b1);
            mma16832(acc[tt][1], a0, a1, a2, a3, b2, b3);
          }
        }
      }
    };

    if (diag) {
      // D = A.A^T: 4-stage pipeline, 3-chunk prefetch, 1 sync/chunk.
#pragma unroll
      for (int s = 0; s < NSTG - 1; s++) {
        int off = s * KC;
#pragma unroll
        for (int q = 0; q < 2; q++) cpa16(stu[s] + soff[q], srcA[q] + off);
        cp_commit();
      }
      for (int ch = 0; ch < NCHUNK; ch++) {
        cp_wait<NSTG - 2>();        // oldest pending group (chunk ch) complete
        __syncthreads();            // stage (ch+3)&3 consumed by all (ch-1 done)
        int pre = ch + NSTG - 1;
        if (pre < NCHUNK) {
          int off = pre * KC;
          uint32_t nxt = stu[pre & (NSTG - 1)];
#pragma unroll
          for (int q = 0; q < 2; q++) cpa16(nxt + soff[q], srcA[q] + off);
        }
        cp_commit();                // always commit: keeps group counting uniform
        uint32_t cur = stu[ch & (NSTG - 1)];
        compute(cur, cur);          // B fragments from the same A tile
      }
      cp_wait<0>();
    } else {
      // off-diagonal (class > 128 rows; rare): A/B serial in stages 0/1
      for (int ch = 0; ch < NCHUNK; ch++) {
        int off = ch * KC;
#pragma unroll
        for (int q = 0; q < 2; q++) cpa16(stu[0] + soff[q], srcA[q] + off);
#pragma unroll
        for (int q = 0; q < 2; q++) cpa16(stu[1] + soff[q], srcB[q] + off);
        cp_commit();
        cp_wait<0>();
        __syncthreads();
        compute(stu[0], stu[1]);
        __syncthreads();
      }
    }

    // epilogue: per tile, frag c0=(r0,n0), c1=(r0,n0+1), c2=(r1,n0), c3=(r1,n0+1)
    {
      float inv = 1.0f / ((float)CC * PSCALE * PSCALE);   // undo fp8 scale + /n_cats
      int gid = lid >> 2, tg = lid & 3;
#pragma unroll
      for (int tt = 0; tt < NT; tt++) {
        if (!tV[tt]) continue;
        bool dtile = diag && (tI[tt] == tJ[tt]);   // on-diagonal tile: single order
        int r0 = tI[tt] * 16 + gid, r1 = r0 + 8;
#pragma unroll
        for (int mhalf = 0; mhalf < 2; mhalf++) {
          int n0 = tJ[tt] * 16 + mhalf * 8 + tg * 2;
#pragma unroll
          for (int e2 = 0; e2 < 4; e2++) {
            int rr = (e2 & 2) ? r1 : r0;
            int cl = n0 + (e2 & 1);
            if (rr < gA && cl < gB) {
              float cross = acc[tt][mhalf][e2] * inv;
              if (dtile) {
                if (rr != cl) { float d = sTB[cl] - cross; local += d * d; }
              } else {
                // tile covers (rr,cl); symmetric partner (cl,rr) also valid pair
                float d1 = sTB[cl] - cross;
                float d2 = sTA[rr] - cross;
                local += d1 * d1 + d2 * d2;
              }
            }
          }
        }
      }
    }
  }

  // ---- block reduce, publish partial, last-CTA final reduce ----
  local = warpSumf(local);
  if (lid == 0) rs[wid] = local;
  __syncthreads();
  float total = 0.0f;
  if (tid == 0) {
#pragma unroll
    for (int w = 0; w < 16; w++) total += rs[w];
    g_partial[c] = total;
    __threadfence();
    int old = atomicAdd(&g_done, 1);
    sLast = (old == NCLS - 1) ? 1 : 0;
  }
  __syncthreads();
  if (sLast) {
    float s = 0.0f;
    for (int i = tid; i < NCLS; i += 512) s += g_partial[i];
    s = warpSumf(s);
    if (lid == 0) rs[wid] = s;
    __syncthreads();
    if (tid == 0) {
      float tot = 0.0f;
#pragma unroll
      for (int w = 0; w < 16; w++) tot += rs[w];
      out[0] = tot / (float)BB;
      g_done = 0;             // reset for next graph replay
    }
  }
}

extern "C" void kernel_launch(void* const* d_in, const int* in_sizes, int n_in,
                              void* d_out, int out_size) {
  const float* x;
  const int* tgt32;
  if (in_sizes[0] == BB) {       // defensive input-order detection
    tgt32 = (const int*)d_in[0];
    x     = (const float*)d_in[1];
  } else {
    x     = (const float*)d_in[0];
    tgt32 = (const int*)d_in[1];
  }

  softmax_kernel<<<BB / 8, 256>>>(x, tgt32);
  gram_kernel<<<NCLS, 512>>>((float*)d_out);
}

// round 12
// speedup vs baseline: 1.6492x; 1.2449x over previous
#include <cuda_runtime.h>
#include <cuda_bf16.h>
#include <cstdint>

#define BB    8192
#define CC    1024
#define NCLS  100
#define CAP   1024
#define TINV  0.25f      // 1/T, T=4
#define PSCALE 128.0f    // fp8 storage scale: q = p*128 keeps q in e4m3 normal range

// ---- scratch (device globals: no allocations allowed) ----
__device__ uint8_t g_p8[(size_t)BB * CC];         // 8 MB fp8(e4m3) scaled probs
__device__ float g_t[BB];
__device__ int   g_cnt[NCLS];
__device__ int   g_list[NCLS * CAP];
__device__ float g_partial[NCLS];
__device__ int   g_done = 0;                      // reset by last CTA each run

// ---- helpers ----
__device__ __forceinline__ uint32_t pack4_e4m3(float p0, float p1, float p2, float p3) {
  uint16_t lo, hi;
  asm("cvt.rn.satfinite.e4m3x2.f32 %0, %1, %2;" : "=h"(lo) : "f"(p1), "f"(p0));
  asm("cvt.rn.satfinite.e4m3x2.f32 %0, %1, %2;" : "=h"(hi) : "f"(p3), "f"(p2));
  return (uint32_t)lo | ((uint32_t)hi << 16);
}

// 4 e4m3 bytes (one uint32) -> 4 floats. Exact: e4m3 -> f16 -> f32.
// Column-order permutation inside the word is irrelevant (all uses are
// column-symmetric sums with consistent s/u pairing).
__device__ __forceinline__ void cvt4_e4m3(float* f, uint32_t w) {
  uint32_t h0, h1;
  asm("cvt.rn.f16x2.e4m3x2 %0, %1;" : "=r"(h0) : "h"((uint16_t)(w & 0xffff)));
  asm("cvt.rn.f16x2.e4m3x2 %0, %1;" : "=r"(h1) : "h"((uint16_t)(w >> 16)));
  asm("{.reg .f16 l, h; mov.b32 {l, h}, %2; cvt.f32.f16 %0, l; cvt.f32.f16 %1, h;}"
      : "=f"(f[0]), "=f"(f[1]) : "r"(h0));
  asm("{.reg .f16 l, h; mov.b32 {l, h}, %2; cvt.f32.f16 %0, l; cvt.f32.f16 %1, h;}"
      : "=f"(f[2]), "=f"(f[3]) : "r"(h1));
}

__device__ __forceinline__ float warpMaxf(float v) {
#pragma unroll
  for (int o = 16; o > 0; o >>= 1) v = fmaxf(v, __shfl_xor_sync(0xffffffffu, v, o));
  return v;
}
__device__ __forceinline__ float warpSumf(float v) {
#pragma unroll
  for (int o = 16; o > 0; o >>= 1) v += __shfl_xor_sync(0xffffffffu, v, o);
  return v;
}

// exp(z) for z <= 0 via 2^w with degree-7 poly: FMA pipe only, avoids MUFU.EX2.
__device__ __forceinline__ float fast_exp(float z) {
  float w  = z * 1.4426950408889634f;
  float nf = floorf(w);
  float f  = w - nf;
  float r  = 1.5252733e-5f;
  r = fmaf(r, f, 1.5403530e-4f);
  r = fmaf(r, f, 1.3333558e-3f);
  r = fmaf(r, f, 9.6181291e-3f);
  r = fmaf(r, f, 5.5504109e-2f);
  r = fmaf(r, f, 2.4022651e-1f);
  r = fmaf(r, f, 6.9314718e-1f);
  r = fmaf(r, f, 1.0f);
  return r * __int_as_float(((int)nf + 127) << 23);
}

// ---- setup (runs inside softmax CTA 0): dtype probe + class scatter ----
// JAX with x64 disabled silently stores int64-requested targets as int32.
// True LE int64 in [0,100) => every odd 32-bit word of the first BB words is 0.
__device__ __forceinline__ void do_setup(const int* __restrict__ tgt32, int tid) {
  __shared__ int scnt[NCLS];
  __shared__ int nz;
  for (int i = tid; i < NCLS; i += 256) scnt[i] = 0;
  if (tid == 0) nz = 0;
  __syncthreads();

  int c = 0;
  for (int i = tid; i < BB / 2; i += 256)
    if (tgt32[2 * i + 1] != 0) c++;
  if (c) atomicAdd(&nz, 1);
  __syncthreads();
  int stride = (nz == 0) ? 2 : 1;   // 2 => int64 low words

  for (int i = tid; i < BB; i += 256) {
    int cl = tgt32[(size_t)i * stride];
    if ((unsigned)cl < NCLS) {
      int s = atomicAdd(&scnt[cl], 1);
      if (s < CAP) g_list[cl * CAP + s] = i;
    }
  }
  __syncthreads();
  for (int i = tid; i < NCLS; i += 256) g_cnt[i] = scnt[i];
}

// ---------------- softmax + t (warp per row) + embedded setup in CTA 0 ----------------
__global__ void __launch_bounds__(256) softmax_kernel(const float* __restrict__ x,
                                                      const int* __restrict__ tgt32) {
  if (blockIdx.x == 0) do_setup(tgt32, threadIdx.x);

  int wid = threadIdx.x >> 5, lid = threadIdx.x & 31;
  int row = blockIdx.x * 8 + wid;

  const float4* src = reinterpret_cast<const float4*>(x + (size_t)row * CC);
  float y[32];
  float m = -3.4e38f;
#pragma unroll
  for (int q = 0; q < 8; q++) {
    float4 v = src[q * 32 + lid];
    y[4 * q + 0] = v.x * TINV; y[4 * q + 1] = v.y * TINV;
    y[4 * q + 2] = v.z * TINV; y[4 * q + 3] = v.w * TINV;
    m = fmaxf(m, fmaxf(fmaxf(y[4 * q], y[4 * q + 1]), fmaxf(y[4 * q + 2], y[4 * q + 3])));
  }
  m = warpMaxf(m);

  float e[32];
  float s = 0.0f;
#pragma unroll
  for (int i = 0; i < 32; i++) { e[i] = fast_exp(y[i] - m); s += e[i]; }
  s = warpSumf(s);
  float invS = 1.0f / s;
  float lnS  = __logf(s);

  uint32_t* dst = reinterpret_cast<uint32_t*>(g_p8 + (size_t)row * CC);
  float tl = 0.0f;
#pragma unroll
  for (int q = 0; q < 8; q++) {
    float p0 = fmaf(e[4 * q + 0], invS, 1e-8f);
    float p1 = fmaf(e[4 * q + 1], invS, 1e-8f);
    float p2 = fmaf(e[4 * q + 2], invS, 1e-8f);
    float p3 = fmaf(e[4 * q + 3], invS, 1e-8f);
    // log p ~= y - m - lnS (+1e-8 shift perturbs log by ~1e-5 abs -> negligible)
    tl += p0 * (y[4 * q + 0] - m - lnS) + p1 * (y[4 * q + 1] - m - lnS)
        + p2 * (y[4 * q + 2] - m - lnS) + p3 * (y[4 * q + 3] - m - lnS);
    dst[q * 32 + lid] = pack4_e4m3(p0 * PSCALE, p1 * PSCALE, p2 * PSCALE, p3 * PSCALE);
  }
  tl = warpSumf(tl);
  if (lid == 0) g_t[row] = tl * (1.0f / CC);
}

// ---------------- per-class linearized loss (NO GEMM) + fused final reduce ----------
// Expansion of sum over same-label ordered pairs (i != j):
//   sum (t_j - cross_ij)^2 = (g-1)*sum_j t_j^2
//                          - (2/C)*( s.u - sum_j t_j*||p_j||^2 )   [exact]
//                          + sum cross^2                            [~2e-8 rel: dropped]
// where s = sum_i p_i, u = sum_j t_j p_j. O(g*C) instead of O(g^2*C) Gram.
// One CTA per class; 4 row-groups x 128 threads; register accumulators for 8 cols
// each; cross-group combine in smem; single linear block-reduce of all terms.
__global__ void __launch_bounds__(512) reduce_kernel(float* __restrict__ out) {
  int c = blockIdx.x;
  int g = min(g_cnt[c], CAP);

  __shared__ float sS[4][1024];   // 16 KB: per-group s partials
  __shared__ float sU[4][1024];   // 16 KB: per-group u partials
  __shared__ int   sRow[CAP];     // 4 KB
  __shared__ float sTv[CAP];      // 4 KB
  __shared__ float rs[16];
  __shared__ int   sLast;

  int tid = threadIdx.x, wid = tid >> 5, lid = tid & 31;
  int grp = tid >> 7;       // 0..3: row group
  int k   = tid & 127;      // word index (4 fp8 cols per word)

  for (int r = tid; r < g; r += 512) {
    int ro = g_list[c * CAP + r];
    sRow[r] = ro;
    sTv[r]  = g_t[ro];
  }
  __syncthreads();

  float sA[8], uA[8];
#pragma unroll
  for (int i = 0; i < 8; i++) { sA[i] = 0.0f; uA[i] = 0.0f; }
  float nrm = 0.0f;   // partial: sum_j t_j * ||q_j||^2

  // rows grp, grp+4, ... ; unroll by 2 for load-latency overlap
  int r = grp;
  for (; r + 4 < g; r += 8) {
    const uint32_t* row0 = (const uint32_t*)(g_p8 + (size_t)sRow[r] * CC);
    const uint32_t* row1 = (const uint32_t*)(g_p8 + (size_t)sRow[r + 4] * CC);
    uint32_t w00 = row0[k], w01 = row0[k + 128];
    uint32_t w10 = row1[k], w11 = row1[k + 128];
    float t0 = sTv[r], t1 = sTv[r + 4];
    float f[8];
    cvt4_e4m3(f,     w00); cvt4_e4m3(f + 4, w01);
    float q2 = 0.0f;
#pragma unroll
    for (int i = 0; i < 8; i++) {
      sA[i] += f[i];
      uA[i] = fmaf(t0, f[i], uA[i]);
      q2 = fmaf(f[i], f[i], q2);
    }
    nrm = fmaf(t0, q2, nrm);
    cvt4_e4m3(f,     w10); cvt4_e4m3(f + 4, w11);
    q2 = 0.0f;
#pragma unroll
    for (int i = 0; i < 8; i++) {
      sA[i] += f[i];
      uA[i] = fmaf(t1, f[i], uA[i]);
      q2 = fmaf(f[i], f[i], q2);
    }
    nrm = fmaf(t1, q2, nrm);
  }
  for (; r < g; r += 4) {
    const uint32_t* row0 = (const uint32_t*)(g_p8 + (size_t)sRow[r] * CC);
    uint32_t w00 = row0[k], w01 = row0[k + 128];
    float t0 = sTv[r];
    float f[8];
    cvt4_e4m3(f, w00); cvt4_e4m3(f + 4, w01);
    float q2 = 0.0f;
#pragma unroll
    for (int i = 0; i < 8; i++) {
      sA[i] += f[i];
      uA[i] = fmaf(t0, f[i], uA[i]);
      q2 = fmaf(f[i], f[i], q2);
    }
    nrm = fmaf(t0, q2, nrm);
  }

  // t^2 partial
  float tsq = 0.0f;
  for (int rr = tid; rr < g; rr += 512) { float t = sTv[rr]; tsq = fmaf(t, t, tsq); }

  // publish per-group s,u (cols 4k..4k+3 and 512+4k..512+4k+3)
#pragma unroll
  for (int i = 0; i < 4; i++) {
    sS[grp][4 * k + i]       = sA[i];
    sU[grp][4 * k + i]       = uA[i];
    sS[grp][512 + 4 * k + i] = sA[4 + i];
    sU[grp][512 + 4 * k + i] = uA[4 + i];
  }
  __syncthreads();

  // dot partial: each thread owns cols tid and tid+512
  float dot = 0.0f;
#pragma unroll
  for (int j = 0; j < 2; j++) {
    int col = tid + j * 512;
    float sv = (sS[0][col] + sS[1][col]) + (sS[2][col] + sS[3][col]);
    float uv = (sU[0][col] + sU[1][col]) + (sU[2][col] + sU[3][col]);
    dot = fmaf(sv, uv, dot);
  }

  // all terms linear in per-thread partials -> single block reduce
  const float coef = 2.0f / ((float)CC * PSCALE * PSCALE);
  float local = (float)(g - 1) * tsq - coef * (dot - nrm);
  if (g == 0) local = 0.0f;

  local = warpSumf(local);
  if (lid == 0) rs[wid] = local;
  __syncthreads();
  float total = 0.0f;
  if (tid == 0) {
#pragma unroll
    for (int w = 0; w < 16; w++) total += rs[w];
    g_partial[c] = total;
    __threadfence();
    int old = atomicAdd(&g_done, 1);
    sLast = (old == NCLS - 1) ? 1 : 0;
  }
  __syncthreads();
  if (sLast) {
    float s = 0.0f;
    for (int i = tid; i < NCLS; i += 512) s += g_partial[i];
    s = warpSumf(s);
    if (lid == 0) rs[wid] = s;
    __syncthreads();
    if (tid == 0) {
      float tot = 0.0f;
#pragma unroll
      for (int w = 0; w < 16; w++) tot += rs[w];
      out[0] = tot / (float)BB;
      g_done = 0;             // reset for next graph replay
    }
  }
}

extern "C" void kernel_launch(void* const* d_in, const int* in_sizes, int n_in,
                              void* d_out, int out_size) {
  const float* x;
  const int* tgt32;
  if (in_sizes[0] == BB) {       // defensive input-order detection
    tgt32 = (const int*)d_in[0];
    x     = (const float*)d_in[1];
  } else {
    x     = (const float*)d_in[0];
    tgt32 = (const int*)d_in[1];
  }

  softmax_kernel<<<BB / 8, 256>>>(x, tgt32);
  reduce_kernel<<<NCLS, 512>>>((float*)d_out);
}